// round 14
// baseline (speedup 1.0000x reference)
#include <cuda_runtime.h>
#include <math.h>

#define H 128
#define NCHK 8000
#define NVAR 16000
#define EDGES 60000
#define NITER 10
#define LN_EPS 1e-6f

#define RT 128
#define XSTD 132                                       // floats; 132*4=528, %16==0
#define SMEM_G (128 * 128 * 4 + 128 * XSTD * 4)        // 65536 + 67584 = 133120

typedef unsigned long long u64;

// ---------------- scratch ----------------
__device__ float g_hc[NCHK * H];
__device__ float g_hv[NVAR * H];
__device__ float g_Pc[NCHK * 256];
__device__ float g_Pv[NVAR * 256];
__device__ float g_aggc[NCHK * H];
__device__ float g_aggv[NVAR * H];
__device__ float g_updc[NCHK * H];
__device__ float g_updv[NVAR * H];
__device__ float g_xac[NCHK * 384];
__device__ float g_hac[NCHK * 384];
__device__ float g_xav[NVAR * 384];
__device__ float g_hav[NVAR * 384];
__device__ int g_cnt_c[NCHK], g_cnt_v[NVAR];
__device__ int g_rp_c[NCHK + 1], g_rp_v[NVAR + 1];
__device__ int g_cur_c[NCHK], g_cur_v[NVAR];
__device__ int g_el_c[EDGES], g_el_v[EDGES];

__device__ __forceinline__ float elu_f(float x) { return x > 0.f ? x : expm1f(x); }
__device__ __forceinline__ float sig_f(float x) { return 1.f / (1.f + expf(-x)); }

__device__ __forceinline__ u64 pack2(float lo, float hi) {
    u64 p; asm("mov.b64 %0, {%1, %2};" : "=l"(p) : "f"(lo), "f"(hi)); return p;
}
__device__ __forceinline__ void fma2(u64& d, u64 a, u64 b) {
    asm("fma.rn.f32x2 %0, %1, %2, %0;" : "+l"(d) : "l"(a), "l"(b));
}
__device__ __forceinline__ float2 unpack2(u64 p) {
    float2 r; asm("mov.b64 {%0, %1}, %2;" : "=f"(r.x), "=f"(r.y) : "l"(p)); return r;
}

// ================= GEMM building blocks (RT=128, 8 rows x 8 cols per thread) =================
// cg=tid&15 -> cols {4cg..4cg+3} U {64+4cg..}; rg=tid>>4 -> rows 8rg..8rg+7.
__device__ __forceinline__ void loadW(float* Ws, const float* __restrict__ W, int ld, int tid)
{
    #pragma unroll
    for (int idx = tid; idx < 4096; idx += 256) {
        const int k = idx >> 5, cq = idx & 31;
        *(float4*)&Ws[k * 128 + 4 * cq] = *(const float4*)&W[(size_t)k * ld + 4 * cq];
    }
}
__device__ __forceinline__ void gather(float* XsT, const float* __restrict__ A,
                                       int row0, int n, int tid)
{
    if (row0 + RT <= n) {
        const float* base = A + (size_t)row0 * 128;
        #pragma unroll 4
        for (int idx = tid; idx < RT * 128; idx += 256)
            XsT[(idx & 127) * XSTD + (idx >> 7)] = base[idx];
    } else {
        #pragma unroll 4
        for (int idx = tid; idx < RT * 128; idx += 256) {
            int rr = row0 + (idx >> 7); if (rr >= n) rr = n - 1;
            XsT[(idx & 127) * XSTD + (idx >> 7)] = A[(size_t)rr * 128 + (idx & 127)];
        }
    }
}
__device__ __forceinline__ void makeB(u64 bq[4], const float* __restrict__ b, int cg)
{
    if (b) {
        bq[0] = pack2(b[4 * cg],     b[4 * cg + 1]);
        bq[1] = pack2(b[4 * cg + 2], b[4 * cg + 3]);
        bq[2] = pack2(b[64 + 4 * cg],     b[64 + 4 * cg + 1]);
        bq[3] = pack2(b[64 + 4 * cg + 2], b[64 + 4 * cg + 3]);
    } else { bq[0] = bq[1] = bq[2] = bq[3] = 0ull; }
}
template<bool INIT>
__device__ __forceinline__ void kloop8(const float* Ws, const float* XsT, int cg, int rg,
                                       u64 acc[8][4], const u64 bq[4])
{
    if (INIT) {
        #pragma unroll
        for (int p = 0; p < 8; p++)
            #pragma unroll
            for (int q = 0; q < 4; q++) acc[p][q] = bq[q];
    }
    const char* xb = (const char*)(XsT + 8 * rg);
    const char* wb = (const char*)(Ws + 4 * cg);
    #pragma unroll 4
    for (int k = 0; k < 128; k++) {
        const float4 x0 = *(const float4*)(xb);
        const float4 x1 = *(const float4*)(xb + 16);
        const ulonglong2 wA = *(const ulonglong2*)(wb);
        const ulonglong2 wB = *(const ulonglong2*)(wb + 256);
        xb += XSTD * 4;
        wb += 128 * 4;
        const u64 xp[8] = {pack2(x0.x, x0.x), pack2(x0.y, x0.y),
                           pack2(x0.z, x0.z), pack2(x0.w, x0.w),
                           pack2(x1.x, x1.x), pack2(x1.y, x1.y),
                           pack2(x1.z, x1.z), pack2(x1.w, x1.w)};
        const u64 wd[4] = {wA.x, wA.y, wB.x, wB.y};
        #pragma unroll
        for (int p = 0; p < 8; p++)
            #pragma unroll
            for (int q = 0; q < 4; q++) fma2(acc[p][q], xp[p], wd[q]);
    }
}
__device__ __forceinline__ void storeRow(float* o, u64 a0, u64 a1, u64 a2, u64 a3, bool act)
{
    const float2 v0 = unpack2(a0), v1 = unpack2(a1), v2 = unpack2(a2), v3 = unpack2(a3);
    float4 a, b;
    if (act) {
        a = make_float4(elu_f(v0.x), elu_f(v0.y), elu_f(v1.x), elu_f(v1.y));
        b = make_float4(elu_f(v2.x), elu_f(v2.y), elu_f(v3.x), elu_f(v3.y));
    } else {
        a = make_float4(v0.x, v0.y, v1.x, v1.y);
        b = make_float4(v2.x, v2.y, v3.x, v3.y);
    }
    *(float4*)o = a;
    *(float4*)(o + 64) = b;
}

// ---------- generic multi-chunk GEMM (256 threads, RT=128, 1 block/SM) ----------
struct Chunk {
    const float* A; const float* W; const float* bias; float* out;
    int ldw, outW, outOff, n, blk0, bpc;
};
struct Multi { Chunk ch[12]; int nch; };

__global__ void __launch_bounds__(256, 1)
gemmM_kernel(Multi M)
{
    extern __shared__ float sm[];
    float* Ws  = sm;
    float* XsT = sm + 128 * 128;
    const int tid = threadIdx.x;
    const int cg = tid & 15, rg = tid >> 4;

    int c = 0;
    #pragma unroll
    for (int i = 1; i < 12; i++)
        if (i < M.nch && (int)blockIdx.x >= M.ch[i].blk0) c = i;
    const Chunk ch = M.ch[c];
    const int t0 = blockIdx.x - ch.blk0;

    const int nTiles = (ch.n + RT - 1) / RT;
    if (t0 >= nTiles) return;

    loadW(Ws, ch.W, ch.ldw, tid);
    u64 bq[4];
    makeB(bq, ch.bias, cg);

    for (int tile = t0; tile < nTiles; tile += ch.bpc) {
        __syncthreads();
        gather(XsT, ch.A, tile * RT, ch.n, tid);
        __syncthreads();

        u64 acc[8][4];
        kloop8<true>(Ws, XsT, cg, rg, acc, bq);

        #pragma unroll
        for (int p = 0; p < 8; p++) {
            const int row = tile * RT + 8 * rg + p;
            if (row < ch.n)
                storeRow(ch.out + (size_t)row * ch.outW + ch.outOff + 4 * cg,
                         acc[p][0], acc[p][1], acc[p][2], acc[p][3], false);
        }
    }
}

// ---------- fused node-update GEMM (C+V), RT=128, two W stages ----------
__global__ void __launch_bounds__(256, 1)
nodeK_kernel(const float* h0, const float* a0, const float* W0, const float* b0, float* o0, int n0,
             const float* h1, const float* a1, const float* W1, const float* b1, float* o1, int n1,
             int gC)
{
    extern __shared__ float sm[];
    float* Ws  = sm;
    float* XsT = sm + 128 * 128;
    const int tid = threadIdx.x;
    const int cg = tid & 15, rg = tid >> 4;

    const bool isC = (int)blockIdx.x < gC;
    const float* Ah   = isC ? h0 : h1;
    const float* Aa   = isC ? a0 : a1;
    const float* W    = isC ? W0 : W1;
    const float* bias = isC ? b0 : b1;
    float* out        = isC ? o0 : o1;
    const int n       = isC ? n0 : n1;
    const int t0      = isC ? blockIdx.x : blockIdx.x - gC;
    const int bpc     = isC ? gC : gridDim.x - gC;

    const int nTiles = (n + RT - 1) / RT;
    if (t0 >= nTiles) return;

    u64 bq[4];
    makeB(bq, bias, cg);

    for (int tile = t0; tile < nTiles; tile += bpc) {
        __syncthreads();
        loadW(Ws, W, 128, tid);
        gather(XsT, Ah, tile * RT, n, tid);
        __syncthreads();

        u64 acc[8][4];
        kloop8<true>(Ws, XsT, cg, rg, acc, bq);

        __syncthreads();
        loadW(Ws, W + 128 * 128, 128, tid);
        gather(XsT, Aa, tile * RT, n, tid);
        __syncthreads();
        kloop8<false>(Ws, XsT, cg, rg, acc, bq);

        #pragma unroll
        for (int p = 0; p < 8; p++) {
            const int row = tile * RT + 8 * rg + p;
            if (row < n)
                storeRow(out + (size_t)row * 128 + 4 * cg,
                         acc[p][0], acc[p][1], acc[p][2], acc[p][3], true);
        }
    }
}

// ---------------- fused aggregate (C + V) ----------------
__global__ void agg2_kernel(const int* __restrict__ rpc, const int* __restrict__ elc,
                            const float* __restrict__ Pv_, const float* __restrict__ Pc_,
                            const float* __restrict__ bmc, float* __restrict__ aggc_,
                            const int* __restrict__ rpv, const int* __restrict__ elv,
                            const float* __restrict__ bmv, float* __restrict__ aggv_, int NC)
{
    const int b = blockIdx.x;
    const int j = threadIdx.x;
    int t; const int* rowptr; const int* srcs; const float* Psend; const float* Ptgt;
    const float* bias; float* out;
    if (b < NC) { t = b; rowptr = rpc; srcs = elc; Psend = Pv_; Ptgt = Pc_; bias = bmc; out = aggc_; }
    else { t = b - NC; rowptr = rpv; srcs = elv; Psend = Pc_; Ptgt = Pv_; bias = bmv; out = aggv_; }

    const float base = Ptgt[(size_t)t * 256 + 128 + j] + bias[j];
    const int beg = rowptr[t], end = rowptr[t + 1];
    float s0 = 0.f, s1 = 0.f;
    int i = beg;
    for (; i + 1 < end; i += 2) {
        const int a = srcs[i], b2 = srcs[i + 1];
        s0 += elu_f(base + Psend[(size_t)a  * 256 + j]);
        s1 += elu_f(base + Psend[(size_t)b2 * 256 + j]);
    }
    if (i < end) s0 += elu_f(base + Psend[(size_t)srcs[i] * 256 + j]);
    out[(size_t)t * 128 + j] = s0 + s1;
}

// ---------------- fused GRU combine (C + V) ----------------
__global__ void combine2_kernel(const float* __restrict__ xac_, const float* __restrict__ hac_,
                                float* __restrict__ hc_,
                                const float* __restrict__ xav_, const float* __restrict__ hav_,
                                float* __restrict__ hv_, int NC, int total)
{
    const int idx = blockIdx.x * blockDim.x + threadIdx.x;
    if (idx >= total * 32) return;
    int n = idx >> 5;
    const int q = (idx & 31) * 4;
    const float* xa; const float* ha; float* h;
    if (n < NC) { xa = xac_; ha = hac_; h = hc_; }
    else { n -= NC; xa = xav_; ha = hav_; h = hv_; }

    const float4 xz = *(const float4*)&xa[(size_t)n * 384 + q];
    const float4 xr = *(const float4*)&xa[(size_t)n * 384 + 128 + q];
    const float4 xh = *(const float4*)&xa[(size_t)n * 384 + 256 + q];
    const float4 hz = *(const float4*)&ha[(size_t)n * 384 + q];
    const float4 hr = *(const float4*)&ha[(size_t)n * 384 + 128 + q];
    const float4 hh = *(const float4*)&ha[(size_t)n * 384 + 256 + q];
    float4 ho = *(const float4*)&h[(size_t)n * 128 + q];

    float z, r, c;
    z = sig_f(xz.x + hz.x); r = sig_f(xr.x + hr.x); c = tanhf(xh.x + r * hh.x); ho.x = z * ho.x + (1.f - z) * c;
    z = sig_f(xz.y + hz.y); r = sig_f(xr.y + hr.y); c = tanhf(xh.y + r * hh.y); ho.y = z * ho.y + (1.f - z) * c;
    z = sig_f(xz.z + hz.z); r = sig_f(xr.z + hr.z); c = tanhf(xh.z + r * hh.z); ho.z = z * ho.z + (1.f - z) * c;
    z = sig_f(xz.w + hz.w); r = sig_f(xr.w + hr.w); c = tanhf(xh.w + r * hh.w); ho.w = z * ho.w + (1.f - z) * c;
    *(float4*)&h[(size_t)n * 128 + q] = ho;
}

// ---------------- init (fused C+V) ----------------
__global__ void init_kernel(const float* cf, const float* vf,
                            const float* Wc, const float* bc, const float* gc, const float* blc,
                            const float* Wv, const float* bv, const float* gv, const float* blv,
                            float* hc, float* hv, int* cntc, int* cntv, int NC)
{
    __shared__ float red[4], red2[4];
    const int b = blockIdx.x, j = threadIdx.x;
    const float* feat; const float* Win; const float* bin; const float* g; const float* bln;
    float* hp; int node;
    if (b < NC) { if (j == 0) cntc[b] = 0; feat = cf; Win = Wc; bin = bc; g = gc; bln = blc; hp = hc; node = b; }
    else { const int bb = b - NC; if (j == 0) cntv[bb] = 0; feat = vf; Win = Wv; bin = bv; g = gv; bln = blv; hp = hv; node = bb; }

    const float val = 0.1f * feat[node] * Win[j] + bin[j];
    float s = val;
    #pragma unroll
    for (int o = 16; o > 0; o >>= 1) s += __shfl_xor_sync(0xffffffff, s, o);
    if ((j & 31) == 0) red[j >> 5] = s;
    __syncthreads();
    const float m = (red[0] + red[1] + red[2] + red[3]) * (1.0f / 128.0f);
    const float d = val - m;
    float s2 = d * d;
    #pragma unroll
    for (int o = 16; o > 0; o >>= 1) s2 += __shfl_xor_sync(0xffffffff, s2, o);
    if ((j & 31) == 0) red2[j >> 5] = s2;
    __syncthreads();
    const float v = (red2[0] + red2[1] + red2[2] + red2[3]) * (1.0f / 128.0f);
    hp[(size_t)node * H + j] = g[j] * d * rsqrtf(v + LN_EPS) + bln[j];
}

// ---------------- CSR ----------------
__global__ void hist_kernel(const int* t1, int* c1, const int* t2, int* c2, int nE, int gHalf)
{
    int b = blockIdx.x;
    const int* tgt; int* cnt;
    if (b < gHalf) { tgt = t1; cnt = c1; } else { tgt = t2; cnt = c2; b -= gHalf; }
    const int e = b * blockDim.x + threadIdx.x;
    if (e < nE) atomicAdd(&cnt[tgt[e]], 1);
}

__device__ void scan_impl(const int* cnt, int* rowptr, int* cursor, int n)
{
    __shared__ int wsum[32];
    __shared__ int tot_s;
    const int tid = threadIdx.x, lane = tid & 31, w = tid >> 5;
    int carry = 0;
    for (int base = 0; base < n; base += 1024) {
        const int i = base + tid;
        int x = (i < n) ? cnt[i] : 0;
        int v = x;
        #pragma unroll
        for (int off = 1; off < 32; off <<= 1) {
            int t = __shfl_up_sync(0xffffffff, v, off);
            if (lane >= off) v += t;
        }
        if (lane == 31) wsum[w] = v;
        __syncthreads();
        if (w == 0) {
            int t = wsum[lane];
            #pragma unroll
            for (int off = 1; off < 32; off <<= 1) {
                int u = __shfl_up_sync(0xffffffff, t, off);
                if (lane >= off) t += u;
            }
            wsum[lane] = t;
            if (lane == 31) tot_s = t;
        }
        __syncthreads();
        const int incl = v + (w > 0 ? wsum[w - 1] : 0);
        if (i < n) { const int ex = carry + incl - x; rowptr[i] = ex; cursor[i] = ex; }
        carry += tot_s;
        __syncthreads();
    }
    if (tid == 0) rowptr[n] = carry;
}

__global__ void scan2_kernel(const int* cA, int* rA, int* uA, int nA,
                             const int* cB, int* rB, int* uB, int nB)
{
    if (blockIdx.x == 0) scan_impl(cA, rA, uA, nA);
    else                 scan_impl(cB, rB, uB, nB);
}

__global__ void fill_kernel(const int* s1, const int* t1, int* u1, int* l1,
                            const int* s2, const int* t2, int* u2, int* l2, int nE, int gHalf)
{
    int b = blockIdx.x;
    const int* src; const int* tgt; int* cur; int* list;
    if (b < gHalf) { src = s1; tgt = t1; cur = u1; list = l1; }
    else           { src = s2; tgt = t2; cur = u2; list = l2; b -= gHalf; }
    const int e = b * blockDim.x + threadIdx.x;
    if (e < nE) { const int p = atomicAdd(&cur[tgt[e]], 1); list[p] = src[e]; }
}

// ---------------- final ----------------
__global__ void final_kernel(const float* __restrict__ hv, const float* __restrict__ Wf,
                             const float* __restrict__ bf, float* __restrict__ out, int n)
{
    const int gw = (blockIdx.x * blockDim.x + threadIdx.x) >> 5;
    const int lane = threadIdx.x & 31;
    if (gw >= n) return;
    const float* row = hv + (size_t)gw * H;
    float s = row[lane] * Wf[lane] + row[lane + 32] * Wf[lane + 32]
            + row[lane + 64] * Wf[lane + 64] + row[lane + 96] * Wf[lane + 96];
    #pragma unroll
    for (int o = 16; o > 0; o >>= 1) s += __shfl_xor_sync(0xffffffff, s, o);
    if (lane == 0) out[gw] = s + bf[0];
}

// ---------------- host ----------------
static inline Chunk mkChunk(const float* A, const float* W, const float* bias, float* out,
                            int ldw, int outW, int outOff, int n, int blk0, int bpc)
{
    Chunk c; c.A = A; c.W = W; c.bias = bias; c.out = out;
    c.ldw = ldw; c.outW = outW; c.outOff = outOff; c.n = n; c.blk0 = blk0; c.bpc = bpc;
    return c;
}

extern "C" void kernel_launch(void* const* d_in, const int* in_sizes, int n_in,
                              void* d_out, int out_size)
{
    const float* check_feats = (const float*)d_in[0];
    const float* var_feats   = (const float*)d_in[1];
    const int*   c2v_src = (const int*)d_in[2];
    const int*   c2v_tgt = (const int*)d_in[3];
    const int*   v2c_src = (const int*)d_in[4];
    const int*   v2c_tgt = (const int*)d_in[5];
    const float* Wc_in = (const float*)d_in[6];
    const float* bc_in = (const float*)d_in[7];
    const float* Wv_in = (const float*)d_in[8];
    const float* bv_in = (const float*)d_in[9];
    const float* gc_ln = (const float*)d_in[10];
    const float* bc_ln = (const float*)d_in[11];
    const float* gv_ln = (const float*)d_in[12];
    const float* bv_ln = (const float*)d_in[13];
    const float* Wmsg_c = (const float*)d_in[14];
    const float* bmsg_c = (const float*)d_in[15];
    const float* Wmsg_v = (const float*)d_in[16];
    const float* bmsg_v = (const float*)d_in[17];
    const float* Wns_c = (const float*)d_in[18];
    const float* bns_c = (const float*)d_in[19];
    const float* Wns_v = (const float*)d_in[20];
    const float* bns_v = (const float*)d_in[21];
    const float* Wg_c = (const float*)d_in[22];
    const float* Ug_c = (const float*)d_in[23];
    const float* bg_c = (const float*)d_in[24];
    const float* Wg_v = (const float*)d_in[25];
    const float* Ug_v = (const float*)d_in[26];
    const float* bg_v = (const float*)d_in[27];
    const float* Wf = (const float*)d_in[28];
    const float* bf = (const float*)d_in[29];

    const int NCn = in_sizes[0];
    const int NVn = in_sizes[1];
    const int E   = in_sizes[2];

    float *hc, *hv, *Pc, *Pv, *aggc, *aggv, *updc, *updv, *xac, *hac, *xav, *hav;
    int *cnt_c, *cnt_v, *rp_c, *rp_v, *cur_c, *cur_v, *el_c, *el_v;
    cudaGetSymbolAddress((void**)&hc, g_hc);
    cudaGetSymbolAddress((void**)&hv, g_hv);
    cudaGetSymbolAddress((void**)&Pc, g_Pc);
    cudaGetSymbolAddress((void**)&Pv, g_Pv);
    cudaGetSymbolAddress((void**)&aggc, g_aggc);
    cudaGetSymbolAddress((void**)&aggv, g_aggv);
    cudaGetSymbolAddress((void**)&updc, g_updc);
    cudaGetSymbolAddress((void**)&updv, g_updv);
    cudaGetSymbolAddress((void**)&xac, g_xac);
    cudaGetSymbolAddress((void**)&hac, g_hac);
    cudaGetSymbolAddress((void**)&xav, g_xav);
    cudaGetSymbolAddress((void**)&hav, g_hav);
    cudaGetSymbolAddress((void**)&cnt_c, g_cnt_c);
    cudaGetSymbolAddress((void**)&cnt_v, g_cnt_v);
    cudaGetSymbolAddress((void**)&rp_c, g_rp_c);
    cudaGetSymbolAddress((void**)&rp_v, g_rp_v);
    cudaGetSymbolAddress((void**)&cur_c, g_cur_c);
    cudaGetSymbolAddress((void**)&cur_v, g_cur_v);
    cudaGetSymbolAddress((void**)&el_c, g_el_c);
    cudaGetSymbolAddress((void**)&el_v, g_el_v);

    cudaFuncSetAttribute(gemmM_kernel, cudaFuncAttributeMaxDynamicSharedMemorySize, SMEM_G);
    cudaFuncSetAttribute(nodeK_kernel, cudaFuncAttributeMaxDynamicSharedMemorySize, SMEM_G);

    const int gEh = (E + 255) / 256;
    const int tV = (NVn + RT - 1) / RT;   // 125
    const int tC = (NCn + RT - 1) / RT;   // 63

    // msg Multi: one tile per block. grid = 2*tV + 2*tC = 376.
    Multi Mmsg; Mmsg.nch = 4;
    Mmsg.ch[0] = mkChunk(hv, Wmsg_c,           nullptr, Pv, 128, 256, 0,   NVn, 0,          tV);
    Mmsg.ch[1] = mkChunk(hv, Wmsg_v + 128*128, nullptr, Pv, 128, 256, 128, NVn, tV,         tV);
    Mmsg.ch[2] = mkChunk(hc, Wmsg_v,           nullptr, Pc, 128, 256, 0,   NCn, 2*tV,       tC);
    Mmsg.ch[3] = mkChunk(hc, Wmsg_c + 128*128, nullptr, Pc, 128, 256, 128, NCn, 2*tV + tC,  tC);
    const int gMsg = 2 * tV + 2 * tC;

    // gru Multi: 12 chunks, one tile per block. grid = 6*tV + 6*tC = 1128.
    Multi Mgru; Mgru.nch = 12;
    for (int g = 0; g < 3; g++) {
        Mgru.ch[g]   = mkChunk(updv, Wg_v + g*128, bg_v + g*128,       xav, 384, 384, g*128, NVn, g*tV,            tV);
        Mgru.ch[3+g] = mkChunk(hv,   Ug_v + g*128, bg_v + 384 + g*128, hav, 384, 384, g*128, NVn, (3+g)*tV,        tV);
        Mgru.ch[6+g] = mkChunk(updc, Wg_c + g*128, bg_c + g*128,       xac, 384, 384, g*128, NCn, 6*tV + g*tC,     tC);
        Mgru.ch[9+g] = mkChunk(hc,   Ug_c + g*128, bg_c + 384 + g*128, hac, 384, 384, g*128, NCn, 6*tV + (3+g)*tC, tC);
    }
    const int gGru = 6 * tV + 6 * tC;

    // setup: 3 launches so gemmM(Mmsg) is my launch #4 (= ncu's #6)
    init_kernel<<<NCn + NVn, 128>>>(check_feats, var_feats,
                                    Wc_in, bc_in, gc_ln, bc_ln,
                                    Wv_in, bv_in, gv_ln, bv_ln,
                                    hc, hv, cnt_c, cnt_v, NCn);
    hist_kernel<<<2 * gEh, 256>>>(v2c_tgt, cnt_c, c2v_tgt, cnt_v, E, gEh);
    scan2_kernel<<<2, 1024>>>(cnt_c, rp_c, cur_c, NCn, cnt_v, rp_v, cur_v, NVn);

    const int total = NCn + NVn;
    bool first = true;
    for (int it = 0; it < NITER; it++) {
        gemmM_kernel<<<gMsg, 256, SMEM_G>>>(Mmsg);
        if (first) {
            fill_kernel<<<2 * gEh, 256>>>(v2c_src, v2c_tgt, cur_c, el_c,
                                          c2v_src, c2v_tgt, cur_v, el_v, E, gEh);
            first = false;
        }
        agg2_kernel<<<total, 128>>>(rp_c, el_c, Pv, Pc, bmsg_c, aggc,
                                    rp_v, el_v, bmsg_v, aggv, NCn);
        nodeK_kernel<<<tC + tV, 256, SMEM_G>>>(hc, aggc, Wns_c, bns_c, updc, NCn,
                                               hv, aggv, Wns_v, bns_v, updv, NVn, tC);
        gemmM_kernel<<<gGru, 256, SMEM_G>>>(Mgru);
        combine2_kernel<<<(total * 32 + 255) / 256, 256>>>(xac, hac, hc, xav, hav, hv, NCn, total);
    }

    final_kernel<<<(NVn * 32 + 127) / 128, 128>>>(hv, Wf, bf, (float*)d_out, NVn);
}

// round 15
// speedup vs baseline: 1.3470x; 1.3470x over previous
#include <cuda_runtime.h>
#include <math.h>

#define H 128
#define NCHK 8000
#define NVAR 16000
#define EDGES 60000
#define NITER 10
#define LN_EPS 1e-6f

#define RT 64
#define XSTD 68                                        // floats; 68*4=272 -> 16B-aligned rows
#define SMEM_N (128 * 128 * 4 + 128 * XSTD * 4)        // 100,352 -> 2 blocks/SM
#define SMEM_K (2 * 128 * 128 * 4 + 128 * XSTD * 4)    // 165,888 -> 1 block/SM

typedef unsigned long long u64;

// ---------------- scratch ----------------
__device__ float g_hc[NCHK * H];
__device__ float g_hv[NVAR * H];
__device__ float g_Pc[NCHK * 256];
__device__ float g_Pv[NVAR * 256];
__device__ float g_aggc[NCHK * H];
__device__ float g_aggv[NVAR * H];
__device__ float g_updc[NCHK * H];
__device__ float g_updv[NVAR * H];
__device__ float g_xac[NCHK * 384];
__device__ float g_hac[NCHK * 384];
__device__ float g_xav[NVAR * 384];
__device__ float g_hav[NVAR * 384];
__device__ int g_cnt_c[NCHK], g_cnt_v[NVAR];
__device__ int g_rp_c[NCHK + 1], g_rp_v[NVAR + 1];
__device__ int g_cur_c[NCHK], g_cur_v[NVAR];
__device__ int g_el_c[EDGES], g_el_v[EDGES];

__device__ __forceinline__ float elu_f(float x) { return x > 0.f ? x : expm1f(x); }
__device__ __forceinline__ float sig_f(float x) { return 1.f / (1.f + expf(-x)); }

__device__ __forceinline__ u64 pack2(float lo, float hi) {
    u64 p; asm("mov.b64 %0, {%1, %2};" : "=l"(p) : "f"(lo), "f"(hi)); return p;
}
__device__ __forceinline__ void fma2(u64& d, u64 a, u64 b) {
    asm("fma.rn.f32x2 %0, %1, %2, %0;" : "+l"(d) : "l"(a), "l"(b));
}
__device__ __forceinline__ float2 unpack2(u64 p) {
    float2 r; asm("mov.b64 {%0, %1}, %2;" : "=f"(r.x), "=f"(r.y) : "l"(p)); return r;
}

// ================= GEMM building blocks =================
// 256 threads. half = tid>>7 -> col offset 64*half. t = tid&127:
//   cq = t&15 -> 4 contiguous cols colOff+4cq..+3 ; rg = t>>4 -> rows 8rg..8rg+7.
// Per k: X read as 2 broadcast LDS.128 giving 4 NATURAL row-pair u64s (no packs);
//        W read as 1 LDS.128 (4 cols, 256B span/warp) + 4 (w,w) packs.
__device__ __forceinline__ void loadW(float* Ws, const float* __restrict__ W, int ld, int tid)
{
    #pragma unroll
    for (int idx = tid; idx < 4096; idx += 256) {
        const int k = idx >> 5, cq = idx & 31;
        *(float4*)&Ws[k * 128 + 4 * cq] = *(const float4*)&W[(size_t)k * ld + 4 * cq];
    }
}
__device__ __forceinline__ void prefetchA(float v[32], const float* __restrict__ A,
                                          int row0, int n, int tid)
{
    if (row0 + RT <= n) {
        const float* base = A + (size_t)row0 * 128;
        #pragma unroll
        for (int i = 0; i < 32; i++) v[i] = base[tid + (i << 8)];
    } else {
        #pragma unroll
        for (int i = 0; i < 32; i++) {
            const int idx = tid + (i << 8);
            int rr = row0 + (idx >> 7); if (rr >= n) rr = n - 1;
            v[i] = A[(size_t)rr * 128 + (idx & 127)];
        }
    }
}
__device__ __forceinline__ void commitX(float* XsT, const float v[32], int tid)
{
    #pragma unroll
    for (int i = 0; i < 32; i++) {
        const int idx = tid + (i << 8);
        XsT[(idx & 127) * XSTD + (idx >> 7)] = v[i];
    }
}
// bias: u64 lanes are (row_even,row_odd) of SAME col -> duplicate per col
__device__ __forceinline__ void makeB(u64 bq[4], const float* __restrict__ b, int col0)
{
    #pragma unroll
    for (int q = 0; q < 4; q++)
        bq[q] = b ? pack2(b[col0 + q], b[col0 + q]) : 0ull;
}
template<bool INIT>
__device__ __forceinline__ void kloop(const float* Ws, const float* XsT, int col0, int rg,
                                      u64 acc[4][4], const u64 bq[4])
{
    if (INIT) {
        #pragma unroll
        for (int p = 0; p < 4; p++)
            #pragma unroll
            for (int q = 0; q < 4; q++) acc[p][q] = bq[q];
    }
    const char* xb = (const char*)(XsT + 8 * rg);
    const char* wb = (const char*)(Ws + col0);
    #pragma unroll 8
    for (int k = 0; k < 128; k++) {
        const ulonglong2 xA = *(const ulonglong2*)(xb);        // rows 8rg..8rg+3 (2 nat pairs)
        const ulonglong2 xB = *(const ulonglong2*)(xb + 16);   // rows 8rg+4..8rg+7
        const float4 w = *(const float4*)(wb);                 // 4 contiguous cols
        xb += XSTD * 4;
        wb += 128 * 4;
        const u64 xp[4] = {xA.x, xA.y, xB.x, xB.y};
        const u64 wd[4] = {pack2(w.x, w.x), pack2(w.y, w.y),
                           pack2(w.z, w.z), pack2(w.w, w.w)};
        #pragma unroll
        for (int p = 0; p < 4; p++)
            #pragma unroll
            for (int q = 0; q < 4; q++) fma2(acc[p][q], xp[p], wd[q]);
    }
}
// store one row-pair: acc[p][q] lanes = (even,odd) row vals for col q
__device__ __forceinline__ void storePair(float* oe, float* oo, bool we, bool wo,
                                          u64 a0, u64 a1, u64 a2, u64 a3, bool act)
{
    const float2 v0 = unpack2(a0), v1 = unpack2(a1), v2 = unpack2(a2), v3 = unpack2(a3);
    if (we) {
        float4 a = make_float4(v0.x, v1.x, v2.x, v3.x);
        if (act) { a.x = elu_f(a.x); a.y = elu_f(a.y); a.z = elu_f(a.z); a.w = elu_f(a.w); }
        *(float4*)oe = a;
    }
    if (wo) {
        float4 a = make_float4(v0.y, v1.y, v2.y, v3.y);
        if (act) { a.x = elu_f(a.x); a.y = elu_f(a.y); a.z = elu_f(a.z); a.w = elu_f(a.w); }
        *(float4*)oo = a;
    }
}

// ---------- generic multi-chunk weight-stationary GEMM (256 threads, 2 blocks/SM) ----------
struct Chunk {
    const float* A; const float* W; const float* bias; float* out;
    int ldw, outW, outOff, n, blk0, bpc;
};
struct Multi { Chunk ch[12]; int nch; };

__global__ void __launch_bounds__(256, 2)
gemmM_kernel(Multi M)
{
    extern __shared__ float sm[];
    float* Ws  = sm;
    float* XsT = sm + 128 * 128;
    const int tid = threadIdx.x;
    const int t = tid & 127;
    const int col0 = (tid >> 7) * 64 + (t & 15) * 4;
    const int rg = t >> 4;

    int c = 0;
    #pragma unroll
    for (int i = 1; i < 12; i++)
        if (i < M.nch && (int)blockIdx.x >= M.ch[i].blk0) c = i;
    const Chunk ch = M.ch[c];
    const int t0 = blockIdx.x - ch.blk0;

    loadW(Ws, ch.W, ch.ldw, tid);
    u64 bq[4];
    makeB(bq, ch.bias, col0);

    const int nTiles = (ch.n + RT - 1) / RT;
    if (t0 >= nTiles) return;

    float v[32];
    prefetchA(v, ch.A, t0 * RT, ch.n, tid);
    __syncthreads();
    commitX(XsT, v, tid);
    __syncthreads();

    for (int tile = t0; tile < nTiles; tile += ch.bpc) {
        const int nxt = tile + ch.bpc;
        if (nxt < nTiles) prefetchA(v, ch.A, nxt * RT, ch.n, tid);

        u64 acc[4][4];
        kloop<true>(Ws, XsT, col0, rg, acc, bq);

        #pragma unroll
        for (int p = 0; p < 4; p++) {
            const int re = tile * RT + 8 * rg + 2 * p;
            float* oe = ch.out + (size_t)re * ch.outW + ch.outOff + col0;
            storePair(oe, oe + ch.outW, re < ch.n, re + 1 < ch.n,
                      acc[p][0], acc[p][1], acc[p][2], acc[p][3], false);
        }
        __syncthreads();
        if (nxt < nTiles) {
            commitX(XsT, v, tid);
            __syncthreads();
        }
    }
}

// ---------- fused node-update GEMM (C+V): 1 block/SM, both W halves resident ----------
__global__ void __launch_bounds__(256, 1)
nodeK_kernel(const float* h0, const float* a0, const float* W0, const float* b0, float* o0, int n0,
             const float* h1, const float* a1, const float* W1, const float* b1, float* o1, int n1,
             int gC)
{
    extern __shared__ float sm[];
    float* WsA = sm;
    float* WsB = sm + 128 * 128;
    float* XsT = sm + 2 * 128 * 128;
    const int tid = threadIdx.x;
    const int t = tid & 127;
    const int col0 = (tid >> 7) * 64 + (t & 15) * 4;
    const int rg = t >> 4;

    const bool isC = (int)blockIdx.x < gC;
    const float* Ah   = isC ? h0 : h1;
    const float* Aa   = isC ? a0 : a1;
    const float* W    = isC ? W0 : W1;
    const float* bias = isC ? b0 : b1;
    float* out        = isC ? o0 : o1;
    const int n       = isC ? n0 : n1;
    const int t0      = isC ? blockIdx.x : blockIdx.x - gC;
    const int bpc     = isC ? gC : gridDim.x - gC;

    loadW(WsA, W, 128, tid);
    loadW(WsB, W + 128 * 128, 128, tid);
    u64 bq[4];
    makeB(bq, bias, col0);

    const int nTiles = (n + RT - 1) / RT;
    if (t0 >= nTiles) return;

    float v[32];
    prefetchA(v, Ah, t0 * RT, n, tid);
    __syncthreads();
    commitX(XsT, v, tid);
    __syncthreads();

    for (int tile = t0; tile < nTiles; tile += bpc) {
        prefetchA(v, Aa, tile * RT, n, tid);
        u64 acc[4][4];
        kloop<true>(WsA, XsT, col0, rg, acc, bq);
        __syncthreads();
        commitX(XsT, v, tid);
        __syncthreads();

        const int nxt = tile + bpc;
        if (nxt < nTiles) prefetchA(v, Ah, nxt * RT, n, tid);
        kloop<false>(WsB, XsT, col0, rg, acc, bq);

        #pragma unroll
        for (int p = 0; p < 4; p++) {
            const int re = tile * RT + 8 * rg + 2 * p;
            float* oe = out + (size_t)re * 128 + col0;
            storePair(oe, oe + 128, re < n, re + 1 < n,
                      acc[p][0], acc[p][1], acc[p][2], acc[p][3], true);
        }
        __syncthreads();
        if (nxt < nTiles) {
            commitX(XsT, v, tid);
            __syncthreads();
        }
    }
}

// ---------------- fused aggregate (C + V) ----------------
__global__ void agg2_kernel(const int* __restrict__ rpc, const int* __restrict__ elc,
                            const float* __restrict__ Pv_, const float* __restrict__ Pc_,
                            const float* __restrict__ bmc, float* __restrict__ aggc_,
                            const int* __restrict__ rpv, const int* __restrict__ elv,
                            const float* __restrict__ bmv, float* __restrict__ aggv_, int NC)
{
    const int b = blockIdx.x;
    const int j = threadIdx.x;
    int t; const int* rowptr; const int* srcs; const float* Psend; const float* Ptgt;
    const float* bias; float* out;
    if (b < NC) { t = b; rowptr = rpc; srcs = elc; Psend = Pv_; Ptgt = Pc_; bias = bmc; out = aggc_; }
    else { t = b - NC; rowptr = rpv; srcs = elv; Psend = Pc_; Ptgt = Pv_; bias = bmv; out = aggv_; }

    const float base = Ptgt[(size_t)t * 256 + 128 + j] + bias[j];
    const int beg = rowptr[t], end = rowptr[t + 1];
    float s0 = 0.f, s1 = 0.f;
    int i = beg;
    for (; i + 1 < end; i += 2) {
        const int a = srcs[i], b2 = srcs[i + 1];
        s0 += elu_f(base + Psend[(size_t)a  * 256 + j]);
        s1 += elu_f(base + Psend[(size_t)b2 * 256 + j]);
    }
    if (i < end) s0 += elu_f(base + Psend[(size_t)srcs[i] * 256 + j]);
    out[(size_t)t * 128 + j] = s0 + s1;
}

// ---------------- fused GRU combine (C + V) ----------------
__global__ void combine2_kernel(const float* __restrict__ xac_, const float* __restrict__ hac_,
                                float* __restrict__ hc_,
                                const float* __restrict__ xav_, const float* __restrict__ hav_,
                                float* __restrict__ hv_, int NC, int total)
{
    const int idx = blockIdx.x * blockDim.x + threadIdx.x;
    if (idx >= total * 32) return;
    int n = idx >> 5;
    const int q = (idx & 31) * 4;
    const float* xa; const float* ha; float* h;
    if (n < NC) { xa = xac_; ha = hac_; h = hc_; }
    else { n -= NC; xa = xav_; ha = hav_; h = hv_; }

    const float4 xz = *(const float4*)&xa[(size_t)n * 384 + q];
    const float4 xr = *(const float4*)&xa[(size_t)n * 384 + 128 + q];
    const float4 xh = *(const float4*)&xa[(size_t)n * 384 + 256 + q];
    const float4 hz = *(const float4*)&ha[(size_t)n * 384 + q];
    const float4 hr = *(const float4*)&ha[(size_t)n * 384 + 128 + q];
    const float4 hh = *(const float4*)&ha[(size_t)n * 384 + 256 + q];
    float4 ho = *(const float4*)&h[(size_t)n * 128 + q];

    float z, r, c;
    z = sig_f(xz.x + hz.x); r = sig_f(xr.x + hr.x); c = tanhf(xh.x + r * hh.x); ho.x = z * ho.x + (1.f - z) * c;
    z = sig_f(xz.y + hz.y); r = sig_f(xr.y + hr.y); c = tanhf(xh.y + r * hh.y); ho.y = z * ho.y + (1.f - z) * c;
    z = sig_f(xz.z + hz.z); r = sig_f(xr.z + hr.z); c = tanhf(xh.z + r * hh.z); ho.z = z * ho.z + (1.f - z) * c;
    z = sig_f(xz.w + hz.w); r = sig_f(xr.w + hr.w); c = tanhf(xh.w + r * hh.w); ho.w = z * ho.w + (1.f - z) * c;
    *(float4*)&h[(size_t)n * 128 + q] = ho;
}

// ---------------- init (fused C+V) ----------------
__global__ void init_kernel(const float* cf, const float* vf,
                            const float* Wc, const float* bc, const float* gc, const float* blc,
                            const float* Wv, const float* bv, const float* gv, const float* blv,
                            float* hc, float* hv, int* cntc, int* cntv, int NC)
{
    __shared__ float red[4], red2[4];
    const int b = blockIdx.x, j = threadIdx.x;
    const float* feat; const float* Win; const float* bin; const float* g; const float* bln;
    float* hp; int node;
    if (b < NC) { if (j == 0) cntc[b] = 0; feat = cf; Win = Wc; bin = bc; g = gc; bln = blc; hp = hc; node = b; }
    else { const int bb = b - NC; if (j == 0) cntv[bb] = 0; feat = vf; Win = Wv; bin = bv; g = gv; bln = blv; hp = hv; node = bb; }

    const float val = 0.1f * feat[node] * Win[j] + bin[j];
    float s = val;
    #pragma unroll
    for (int o = 16; o > 0; o >>= 1) s += __shfl_xor_sync(0xffffffff, s, o);
    if ((j & 31) == 0) red[j >> 5] = s;
    __syncthreads();
    const float m = (red[0] + red[1] + red[2] + red[3]) * (1.0f / 128.0f);
    const float d = val - m;
    float s2 = d * d;
    #pragma unroll
    for (int o = 16; o > 0; o >>= 1) s2 += __shfl_xor_sync(0xffffffff, s2, o);
    if ((j & 31) == 0) red2[j >> 5] = s2;
    __syncthreads();
    const float v = (red2[0] + red2[1] + red2[2] + red2[3]) * (1.0f / 128.0f);
    hp[(size_t)node * H + j] = g[j] * d * rsqrtf(v + LN_EPS) + bln[j];
}

// ---------------- CSR ----------------
__global__ void hist_kernel(const int* t1, int* c1, const int* t2, int* c2, int nE, int gHalf)
{
    int b = blockIdx.x;
    const int* tgt; int* cnt;
    if (b < gHalf) { tgt = t1; cnt = c1; } else { tgt = t2; cnt = c2; b -= gHalf; }
    const int e = b * blockDim.x + threadIdx.x;
    if (e < nE) atomicAdd(&cnt[tgt[e]], 1);
}

__device__ void scan_impl(const int* cnt, int* rowptr, int* cursor, int n)
{
    __shared__ int wsum[32];
    __shared__ int tot_s;
    const int tid = threadIdx.x, lane = tid & 31, w = tid >> 5;
    int carry = 0;
    for (int base = 0; base < n; base += 1024) {
        const int i = base + tid;
        int x = (i < n) ? cnt[i] : 0;
        int v = x;
        #pragma unroll
        for (int off = 1; off < 32; off <<= 1) {
            int t = __shfl_up_sync(0xffffffff, v, off);
            if (lane >= off) v += t;
        }
        if (lane == 31) wsum[w] = v;
        __syncthreads();
        if (w == 0) {
            int t = wsum[lane];
            #pragma unroll
            for (int off = 1; off < 32; off <<= 1) {
                int u = __shfl_up_sync(0xffffffff, t, off);
                if (lane >= off) t += u;
            }
            wsum[lane] = t;
            if (lane == 31) tot_s = t;
        }
        __syncthreads();
        const int incl = v + (w > 0 ? wsum[w - 1] : 0);
        if (i < n) { const int ex = carry + incl - x; rowptr[i] = ex; cursor[i] = ex; }
        carry += tot_s;
        __syncthreads();
    }
    if (tid == 0) rowptr[n] = carry;
}

__global__ void scan2_kernel(const int* cA, int* rA, int* uA, int nA,
                             const int* cB, int* rB, int* uB, int nB)
{
    if (blockIdx.x == 0) scan_impl(cA, rA, uA, nA);
    else                 scan_impl(cB, rB, uB, nB);
}

__global__ void fill_kernel(const int* s1, const int* t1, int* u1, int* l1,
                            const int* s2, const int* t2, int* u2, int* l2, int nE, int gHalf)
{
    int b = blockIdx.x;
    const int* src; const int* tgt; int* cur; int* list;
    if (b < gHalf) { src = s1; tgt = t1; cur = u1; list = l1; }
    else           { src = s2; tgt = t2; cur = u2; list = l2; b -= gHalf; }
    const int e = b * blockDim.x + threadIdx.x;
    if (e < nE) { const int p = atomicAdd(&cur[tgt[e]], 1); list[p] = src[e]; }
}

// ---------------- final ----------------
__global__ void final_kernel(const float* __restrict__ hv, const float* __restrict__ Wf,
                             const float* __restrict__ bf, float* __restrict__ out, int n)
{
    const int gw = (blockIdx.x * blockDim.x + threadIdx.x) >> 5;
    const int lane = threadIdx.x & 31;
    if (gw >= n) return;
    const float* row = hv + (size_t)gw * H;
    float s = row[lane] * Wf[lane] + row[lane + 32] * Wf[lane + 32]
            + row[lane + 64] * Wf[lane + 64] + row[lane + 96] * Wf[lane + 96];
    #pragma unroll
    for (int o = 16; o > 0; o >>= 1) s += __shfl_xor_sync(0xffffffff, s, o);
    if (lane == 0) out[gw] = s + bf[0];
}

// ---------------- host ----------------
static inline Chunk mkChunk(const float* A, const float* W, const float* bias, float* out,
                            int ldw, int outW, int outOff, int n, int blk0, int bpc)
{
    Chunk c; c.A = A; c.W = W; c.bias = bias; c.out = out;
    c.ldw = ldw; c.outW = outW; c.outOff = outOff; c.n = n; c.blk0 = blk0; c.bpc = bpc;
    return c;
}

extern "C" void kernel_launch(void* const* d_in, const int* in_sizes, int n_in,
                              void* d_out, int out_size)
{
    const float* check_feats = (const float*)d_in[0];
    const float* var_feats   = (const float*)d_in[1];
    const int*   c2v_src = (const int*)d_in[2];
    const int*   c2v_tgt = (const int*)d_in[3];
    const int*   v2c_src = (const int*)d_in[4];
    const int*   v2c_tgt = (const int*)d_in[5];
    const float* Wc_in = (const float*)d_in[6];
    const float* bc_in = (const float*)d_in[7];
    const float* Wv_in = (const float*)d_in[8];
    const float* bv_in = (const float*)d_in[9];
    const float* gc_ln = (const float*)d_in[10];
    const float* bc_ln = (const float*)d_in[11];
    const float* gv_ln = (const float*)d_in[12];
    const float* bv_ln = (const float*)d_in[13];
    const float* Wmsg_c = (const float*)d_in[14];
    const float* bmsg_c = (const float*)d_in[15];
    const float* Wmsg_v = (const float*)d_in[16];
    const float* bmsg_v = (const float*)d_in[17];
    const float* Wns_c = (const float*)d_in[18];
    const float* bns_c = (const float*)d_in[19];
    const float* Wns_v = (const float*)d_in[20];
    const float* bns_v = (const float*)d_in[21];
    const float* Wg_c = (const float*)d_in[22];
    const float* Ug_c = (const float*)d_in[23];
    const float* bg_c = (const float*)d_in[24];
    const float* Wg_v = (const float*)d_in[25];
    const float* Ug_v = (const float*)d_in[26];
    const float* bg_v = (const float*)d_in[27];
    const float* Wf = (const float*)d_in[28];
    const float* bf = (const float*)d_in[29];

    const int NCn = in_sizes[0];
    const int NVn = in_sizes[1];
    const int E   = in_sizes[2];

    float *hc, *hv, *Pc, *Pv, *aggc, *aggv, *updc, *updv, *xac, *hac, *xav, *hav;
    int *cnt_c, *cnt_v, *rp_c, *rp_v, *cur_c, *cur_v, *el_c, *el_v;
    cudaGetSymbolAddress((void**)&hc, g_hc);
    cudaGetSymbolAddress((void**)&hv, g_hv);
    cudaGetSymbolAddress((void**)&Pc, g_Pc);
    cudaGetSymbolAddress((void**)&Pv, g_Pv);
    cudaGetSymbolAddress((void**)&aggc, g_aggc);
    cudaGetSymbolAddress((void**)&aggv, g_aggv);
    cudaGetSymbolAddress((void**)&updc, g_updc);
    cudaGetSymbolAddress((void**)&updv, g_updv);
    cudaGetSymbolAddress((void**)&xac, g_xac);
    cudaGetSymbolAddress((void**)&hac, g_hac);
    cudaGetSymbolAddress((void**)&xav, g_xav);
    cudaGetSymbolAddress((void**)&hav, g_hav);
    cudaGetSymbolAddress((void**)&cnt_c, g_cnt_c);
    cudaGetSymbolAddress((void**)&cnt_v, g_cnt_v);
    cudaGetSymbolAddress((void**)&rp_c, g_rp_c);
    cudaGetSymbolAddress((void**)&rp_v, g_rp_v);
    cudaGetSymbolAddress((void**)&cur_c, g_cur_c);
    cudaGetSymbolAddress((void**)&cur_v, g_cur_v);
    cudaGetSymbolAddress((void**)&el_c, g_el_c);
    cudaGetSymbolAddress((void**)&el_v, g_el_v);

    cudaFuncSetAttribute(gemmM_kernel, cudaFuncAttributeMaxDynamicSharedMemorySize, SMEM_N);
    cudaFuncSetAttribute(nodeK_kernel, cudaFuncAttributeMaxDynamicSharedMemorySize, SMEM_K);

    const int gEh = (E + 255) / 256;

    // msg Multi: V chunks 100 blocks each, C chunks 48 -> grid 296 (2 blocks/SM).
    Multi Mmsg; Mmsg.nch = 4;
    Mmsg.ch[0] = mkChunk(hv, Wmsg_c,           nullptr, Pv, 128, 256, 0,   NVn, 0,   100);
    Mmsg.ch[1] = mkChunk(hv, Wmsg_v + 128*128, nullptr, Pv, 128, 256, 128, NVn, 100, 100);
    Mmsg.ch[2] = mkChunk(hc, Wmsg_v,           nullptr, Pc, 128, 256, 0,   NCn, 200, 48);
    Mmsg.ch[3] = mkChunk(hc, Wmsg_c + 128*128, nullptr, Pc, 128, 256, 128, NCn, 248, 48);

    // gru Multi: V chunks 32 blocks each (192), C chunks 16 each (96) -> grid 288.
    Multi Mgru; Mgru.nch = 12;
    for (int g = 0; g < 3; g++) {
        Mgru.ch[g]     = mkChunk(updv, Wg_v + g*128, bg_v + g*128,       xav, 384, 384, g*128, NVn, 32*g,        32);
        Mgru.ch[3+g]   = mkChunk(hv,   Ug_v + g*128, bg_v + 384 + g*128, hav, 384, 384, g*128, NVn, 96 + 32*g,   32);
        Mgru.ch[6+g]   = mkChunk(updc, Wg_c + g*128, bg_c + g*128,       xac, 384, 384, g*128, NCn, 192 + 16*g,  16);
        Mgru.ch[9+g]   = mkChunk(hc,   Ug_c + g*128, bg_c + 384 + g*128, hac, 384, 384, g*128, NCn, 240 + 16*g,  16);
    }

    // setup: 3 launches so gemmM(Mmsg) is my launch #4 (= ncu's #6)
    init_kernel<<<NCn + NVn, 128>>>(check_feats, var_feats,
                                    Wc_in, bc_in, gc_ln, bc_ln,
                                    Wv_in, bv_in, gv_ln, bv_ln,
                                    hc, hv, cnt_c, cnt_v, NCn);
    hist_kernel<<<2 * gEh, 256>>>(v2c_tgt, cnt_c, c2v_tgt, cnt_v, E, gEh);
    scan2_kernel<<<2, 1024>>>(cnt_c, rp_c, cur_c, NCn, cnt_v, rp_v, cur_v, NVn);

    const int total = NCn + NVn;
    bool first = true;
    for (int it = 0; it < NITER; it++) {
        gemmM_kernel<<<296, 256, SMEM_N>>>(Mmsg);
        if (first) {
            fill_kernel<<<2 * gEh, 256>>>(v2c_src, v2c_tgt, cur_c, el_c,
                                          c2v_src, c2v_tgt, cur_v, el_v, E, gEh);
            first = false;
        }
        agg2_kernel<<<total, 128>>>(rp_c, el_c, Pv, Pc, bmsg_c, aggc,
                                    rp_v, el_v, bmsg_v, aggv, NCn);
        nodeK_kernel<<<148, 256, SMEM_K>>>(hc, aggc, Wns_c, bns_c, updc, NCn,
                                           hv, aggv, Wns_v, bns_v, updv, NVn, 49);
        gemmM_kernel<<<288, 256, SMEM_N>>>(Mgru);
        combine2_kernel<<<(total * 32 + 255) / 256, 256>>>(xac, hac, hc, xav, hav, hv, NCn, total);
    }

    final_kernel<<<(NVn * 32 + 127) / 128, 128>>>(hv, Wf, bf, (float*)d_out, NVn);
}